// round 14
// baseline (speedup 1.0000x reference)
#include <cuda_runtime.h>
#include <cstddef>

// Problem constants
constexpr int NB = 32;     // batch
constexpr int NS = 2048;   // sequence
constexpr int ND = 512;    // model dim
constexpr int NF = 512;    // dff
constexpr int CH = 32;     // chunks per batch (blocks per batch)
constexpr int ROWS = NS / CH;  // 64 rows per chunk
constexpr int NW = 8;      // warps per block (256 threads)
#define INV_SQRT_DFF 0.044194173824159216f  // 1/sqrt(512)

// Scratch (device globals; statically zero-initialized, no allocation)
__device__ float g_xwp[CH * NB * ND];   // xw partials per chunk
__device__ float g_xw[NB * ND];         // reduced xw
__device__ float g_wsumB[NB];           // per-batch wsum (identical values)
__device__ float g_kw[NB * NF];         // kw
__device__ float g_cp[NB * CH];         // c partials (16-f slices)
__device__ float g_u[NB * ND];          // u
__device__ float g_xtp[CH * NB * ND];   // xt partials
__device__ float g_Tp[CH * NB];
__device__ float g_T[NB];
__device__ float g_xt[NB * ND];
__device__ int   g_cnt1[NB], g_cnt2[NB], g_cnt3[NB], g_cnt4[NB], g_fin[NB];

// ---------------------------------------------------------------------------
// Fused per-batch pipeline. grid = NB*CH blocks (batch-major), 256 threads.
//   A : xw partial from own x chunk (DRAM stream); block c==0 also wsum[b]
//   B1: reduce xw slice (16 d)      [after cnt1==32]
//   B2: kw slice (16 f) + c partial [after cnt2==32]
//   C : u slice (16 d)              [after cnt3==32]
//   D : pass2 on own x chunk -> xt/T partials [after cnt4==32]
// Waits are intra-batch only -> deadlock-free at any occupancy.
// ---------------------------------------------------------------------------
__global__ __launch_bounds__(256) void k_fused(
    const float* __restrict__ x,  const float* __restrict__ Wq,
    const float* __restrict__ bq, const float* __restrict__ Wk,
    const float* __restrict__ bk, const float* __restrict__ Wt,
    const float* __restrict__ bt) {
    const int bid = blockIdx.x;
    const int b = bid >> 5;          // batch
    const int c = bid & 31;          // chunk / slice index
    const int tid = threadIdx.x, warp = tid >> 5, lane = tid & 31;
    const int s0 = c * ROWS;

    __shared__ float  s_wt[ROWS];
    __shared__ float4 s4[NW * 128];      // 16 KB reduce buffer (A and D)
    __shared__ float  s_vec[ND];         // xw (B2) / kw (C) broadcast
    __shared__ float  s_red[256];
    __shared__ float  s_kw16[16];
    __shared__ float  s_cp[CH];
    __shared__ float  s_T[NW];

    // ---------------- Stage A: xw partial ----------------
    if (tid < ROWS) s_wt[tid] = Wt[s0 + tid];
    __syncthreads();

    {
        float4 acc[4] = {{0,0,0,0},{0,0,0,0},{0,0,0,0},{0,0,0,0}};
#pragma unroll 2
        for (int r = warp; r < ROWS; r += NW) {
            const float4* xp = (const float4*)x + ((size_t)b * NS + s0 + r) * (ND / 4);
            const float wt = s_wt[r];
#pragma unroll
            for (int j = 0; j < 4; j++) {
                float4 v = xp[32 * j + lane];
                acc[j].x += wt * v.x; acc[j].y += wt * v.y;
                acc[j].z += wt * v.z; acc[j].w += wt * v.w;
            }
        }
#pragma unroll
        for (int j = 0; j < 4; j++) s4[warp * 128 + 32 * j + lane] = acc[j];
        __syncthreads();

        const float* s = (const float*)s4;
        float v0 = 0.f, v1 = 0.f;
#pragma unroll
        for (int w = 0; w < NW; w++) {
            v0 += s[w * 512 + tid];
            v1 += s[w * 512 + tid + 256];
        }
        float* dst = g_xwp + ((size_t)c * NB + b) * ND;
        dst[tid] = v0;
        dst[tid + 256] = v1;
    }

    // block (b, 0): per-batch wsum (published before cnt1 arrive)
    if (c == 0) {
        float w = 0.f;
#pragma unroll
        for (int k = 0; k < NS / 256; k++) w += Wt[tid + 256 * k];
        s_red[tid] = w;
        __syncthreads();
        if (tid < 32) {
            float t = 0.f;
#pragma unroll
            for (int g = 0; g < 8; g++) t += s_red[tid + 32 * g];
#pragma unroll
            for (int off = 16; off; off >>= 1)
                t += __shfl_xor_sync(0xffffffffu, t, off);
            if (tid == 0) g_wsumB[b] = t;
        }
    }
    __threadfence();
    if (tid == 0) {
        atomicAdd(&g_cnt1[b], 1);
        while (((volatile int*)g_cnt1)[b] < CH) __nanosleep(64);
    }
    __syncthreads();

    // ---------------- Stage B1: reduce xw slice (d in [c*16, c*16+16)) -----
    {
        const int dl = tid & 15, g = tid >> 4;      // g: 0..15, 2 chunks each
        float v = 0.f;
#pragma unroll
        for (int k = 0; k < 2; k++) {
            const int ck = g * 2 + k;
            v += __ldcg(&g_xwp[((size_t)ck * NB + b) * ND + c * 16 + dl]);
        }
        s_red[g * 16 + dl] = v;
        __syncthreads();
        if (tid < 16) {
            float xw = 0.f;
#pragma unroll
            for (int g2 = 0; g2 < 16; g2++) xw += s_red[g2 * 16 + tid];
            g_xw[b * ND + c * 16 + tid] = xw;
        }
    }
    __threadfence();
    if (tid == 0) {
        atomicAdd(&g_cnt2[b], 1);
        while (((volatile int*)g_cnt2)[b] < CH) __nanosleep(64);
    }
    __syncthreads();

    // ---------------- Stage B2: kw slice (f in [c*16, c*16+16)) ------------
    {
        s_vec[tid]       = __ldcg(&g_xw[b * ND + tid]);
        s_vec[tid + 256] = __ldcg(&g_xw[b * ND + tid + 256]);
        const float wsum = __ldcg(&g_wsumB[b]);   // single uniform L2 load
        __syncthreads();

#pragma unroll
        for (int j = 0; j < 2; j++) {
            const int f = c * 16 + warp * 2 + j;
            const float* wk = Wk + (size_t)f * ND;
            float acc = 0.f;
#pragma unroll
            for (int i = 0; i < 16; i++)
                acc += wk[lane + 32 * i] * s_vec[lane + 32 * i];
#pragma unroll
            for (int off = 16; off; off >>= 1)
                acc += __shfl_xor_sync(0xffffffffu, acc, off);
            if (lane == 0) {
                const float kwv = acc + bk[f] * wsum;
                g_kw[b * NF + f] = kwv;
                s_kw16[warp * 2 + j] = kwv;
            }
        }
        __syncthreads();
        if (tid == 0) {
            float cp = 0.f;
#pragma unroll
            for (int i = 0; i < 16; i++) cp += bq[c * 16 + i] * s_kw16[i];
            g_cp[b * CH + c] = cp;
        }
    }
    __threadfence();
    if (tid == 0) {
        atomicAdd(&g_cnt3[b], 1);
        while (((volatile int*)g_cnt3)[b] < CH) __nanosleep(64);
    }
    __syncthreads();

    // ---------------- Stage C: u slice (d in [c*16, c*16+16)) --------------
    {
        s_vec[tid]       = __ldcg(&g_kw[b * NF + tid]);
        s_vec[tid + 256] = __ldcg(&g_kw[b * NF + tid + 256]);
        __syncthreads();

        const int dl = tid & 15, fg = tid >> 4;     // fg: 0..15, 32 f each
        float acc = 0.f;
#pragma unroll
        for (int i = 0; i < 32; i++) {
            const int f = fg * 32 + i;
            acc += Wq[(size_t)f * ND + c * 16 + dl] * s_vec[f];
        }
        __syncthreads();
        s_red[fg * 16 + dl] = acc;
        __syncthreads();
        if (tid < 16) {
            float u = 0.f;
#pragma unroll
            for (int g2 = 0; g2 < 16; g2++) u += s_red[g2 * 16 + tid];
            g_u[b * ND + c * 16 + tid] = u;
        }
    }
    __threadfence();
    if (tid == 0) {
        atomicAdd(&g_cnt4[b], 1);
        while (((volatile int*)g_cnt4)[b] < CH) __nanosleep(64);
    }
    __syncthreads();

    // ---------------- Stage D: pass2 on own x chunk -------------------------
    {
        if (tid < CH) s_cp[tid] = __ldcg(&g_cp[b * CH + tid]);
        float4 u4[4];
        const float4* up = (const float4*)(g_u + b * ND);
#pragma unroll
        for (int j = 0; j < 4; j++) u4[j] = __ldcg(&up[32 * j + lane]);
        __syncthreads();

        float cb = 0.f;
#pragma unroll
        for (int k = 0; k < CH; k++) cb += s_cp[k];   // same fixed order everywhere
        const float btv = bt[0];

        float4 acc[4] = {{0,0,0,0},{0,0,0,0},{0,0,0,0},{0,0,0,0}};
        float tsum = 0.f;

#pragma unroll 2
        for (int r = warp; r < ROWS; r += NW) {
            const float4* xp = (const float4*)x + ((size_t)b * NS + s0 + r) * (ND / 4);
            float4 xv[4];
#pragma unroll
            for (int j = 0; j < 4; j++) xv[j] = xp[32 * j + lane];
            float dot = 0.f;
#pragma unroll
            for (int j = 0; j < 4; j++)
                dot += xv[j].x * u4[j].x + xv[j].y * u4[j].y +
                       xv[j].z * u4[j].z + xv[j].w * u4[j].w;
#pragma unroll
            for (int off = 16; off; off >>= 1)
                dot += __shfl_xor_sync(0xffffffffu, dot, off);
            const float ta = (dot + cb) * INV_SQRT_DFF + btv;
            tsum += ta;
#pragma unroll
            for (int j = 0; j < 4; j++) {
                acc[j].x += ta * xv[j].x; acc[j].y += ta * xv[j].y;
                acc[j].z += ta * xv[j].z; acc[j].w += ta * xv[j].w;
            }
        }
#pragma unroll
        for (int j = 0; j < 4; j++) s4[warp * 128 + 32 * j + lane] = acc[j];
        if (lane == 0) s_T[warp] = tsum;
        __syncthreads();

        const float* s = (const float*)s4;
        float v0 = 0.f, v1 = 0.f;
#pragma unroll
        for (int w = 0; w < NW; w++) {
            v0 += s[w * 512 + tid];
            v1 += s[w * 512 + tid + 256];
        }
        float* dst = g_xtp + ((size_t)c * NB + b) * ND;
        dst[tid] = v0;
        dst[tid + 256] = v1;
        if (tid == 0) {
            float t = 0.f;
#pragma unroll
            for (int w = 0; w < NW; w++) t += s_T[w];
            g_Tp[c * NB + b] = t;
        }
    }

    // ---------------- Reset counters for next graph replay ------------------
    __threadfence();
    if (tid == 0) {
        const int old = atomicAdd(&g_fin[b], 1);
        if (old == CH - 1) {       // last arriver: nobody spins on these anymore
            g_cnt1[b] = 0; g_cnt2[b] = 0;
            g_cnt3[b] = 0; g_cnt4[b] = 0;
            g_fin[b] = 0;
        }
    }
}

// ---------------------------------------------------------------------------
// Reduce xt partials + T partials. grid 32, 512 threads
// ---------------------------------------------------------------------------
__global__ __launch_bounds__(512) void k_red2() {
    const int i = blockIdx.x * 512 + threadIdx.x;
    float v = 0.f;
#pragma unroll
    for (int c = 0; c < CH; c++) v += g_xtp[(size_t)c * NB * ND + i];
    g_xt[i] = v;

    if (blockIdx.x == 0 && threadIdx.x < NB) {
        float t = 0.f;
#pragma unroll
        for (int c = 0; c < CH; c++) t += g_Tp[c * NB + threadIdx.x];
        g_T[threadIdx.x] = t;
    }
}

// ---------------------------------------------------------------------------
// latent[b,f] = Wv[f,:].xt[b,:] + bv[f]*T[b]
// grid (64 f-tiles, 8 b-groups) = 512 blocks, 256 threads, 16 KB smem.
// One f per warp x 4 batches: high occupancy AND Wv reuse (L2 traffic 8 MB).
// ---------------------------------------------------------------------------
__global__ __launch_bounds__(256) void k_out(const float* __restrict__ Wv,
                                             const float* __restrict__ bv,
                                             float* __restrict__ out) {
    const int f0 = blockIdx.x * 8;
    const int b0 = blockIdx.y * 4;
    const int tid = threadIdx.x, warp = tid >> 5, lane = tid & 31;

    __shared__ float s_wv[8 * ND];      // 16 KB
    __shared__ float s_T4[4];

    {   // cooperative coalesced load of the Wv slice (1024 float4)
        const float4* src = (const float4*)(Wv + (size_t)f0 * ND);
        float4* d4 = (float4*)s_wv;
#pragma unroll
        for (int i = 0; i < 4; i++) d4[tid + 256 * i] = src[tid + 256 * i];
    }
    if (tid < 4) s_T4[tid] = g_T[b0 + tid];
    __syncthreads();

    const int f = f0 + warp;
    const float4* wrow = (const float4*)(s_wv + warp * ND);
    float4 w4[4];
#pragma unroll
    for (int q = 0; q < 4; q++) w4[q] = wrow[lane + 32 * q];
    const float bvf = bv[f];

#pragma unroll
    for (int bb = 0; bb < 4; bb++) {
        const int b = b0 + bb;
        const float4* xt4 = (const float4*)(g_xt + b * ND);
        float dot = 0.f;
#pragma unroll
        for (int q = 0; q < 4; q++) {
            float4 xv = xt4[lane + 32 * q];
            dot += w4[q].x * xv.x + w4[q].y * xv.y +
                   w4[q].z * xv.z + w4[q].w * xv.w;
        }
#pragma unroll
        for (int off = 16; off; off >>= 1)
            dot += __shfl_xor_sync(0xffffffffu, dot, off);
        if (lane == 0) out[b * NF + f] = dot + bvf * s_T4[bb];
    }
}

// ---------------------------------------------------------------------------
extern "C" void kernel_launch(void* const* d_in, const int* in_sizes, int n_in,
                              void* d_out, int out_size) {
    const float* x  = (const float*)d_in[0];
    const float* Wq = (const float*)d_in[1];
    const float* bq = (const float*)d_in[2];
    const float* Wk = (const float*)d_in[3];
    const float* bk = (const float*)d_in[4];
    const float* Wv = (const float*)d_in[5];
    const float* bv = (const float*)d_in[6];
    const float* Wt = (const float*)d_in[7];
    const float* bt = (const float*)d_in[8];
    float* out = (float*)d_out;

    k_fused<<<NB * CH, 256>>>(x, Wq, bq, Wk, bk, Wt, bt);
    k_red2 <<<32, 512>>>();
    k_out  <<<dim3(64, 8), 256>>>(Wv, bv, out);
}